// round 3
// baseline (speedup 1.0000x reference)
#include <cuda_runtime.h>
#include <cuda_bf16.h>

// ---------------------------------------------------------------------------
// 2-layer GCN:  out = (Â · relu(Â·(X·W1) + b1) · W2) + b2,  Â = D^-1/2 (A+I) D^-1/2
// Scratch in __device__ globals. Edge dtype (int32 vs int64) detected on-device
// and decoded once into int32 arrays.
// ---------------------------------------------------------------------------

#define NMAX   50048
#define EMAX   800000
#define INF    128
#define OUTF   64

__device__ int   g_is64;
__device__ int   g_src [EMAX];
__device__ int   g_dst [EMAX];
__device__ float g_deg [NMAX];
__device__ float g_dinv[NMAX];
__device__ float g_h1  [NMAX * INF];   // X @ W1
__device__ float g_agg1[NMAX * INF];   // aggregated layer-1 (pre bias/relu)
__device__ float g_h2  [NMAX * OUTF];  // relu(agg1+b1) @ W2

// ---------------------------------------------------------------------------
// dtype probe: view buffer as int32 (always in-bounds for the first `words`
// 32-bit words). int64 indices < 2^31 have all odd (high) words == 0.
// ---------------------------------------------------------------------------
__global__ void k_probe(const int* __restrict__ w32, int words) {
    __shared__ int viol;
    if (threadIdx.x == 0) viol = 0;
    __syncthreads();
    int nchk = words / 2;           // odd positions available
    if (nchk > 32768) nchk = 32768; // sample is plenty
    int bad = 0;
    for (int i = threadIdx.x; i < nchk; i += blockDim.x)
        if (w32[2 * i + 1] != 0) bad = 1;
    if (bad) atomicOr(&viol, 1);
    __syncthreads();
    if (threadIdx.x == 0) g_is64 = (viol == 0) ? 1 : 0;
}

// decode edges into int32 scratch (branch uniform via g_is64)
__global__ void k_decode(const void* __restrict__ ei, int E) {
    int e = blockIdx.x * blockDim.x + threadIdx.x;
    if (e >= E) return;
    if (g_is64) {
        const long long* p = (const long long*)ei;
        g_src[e] = (int)p[e];
        g_dst[e] = (int)p[E + e];
    } else {
        const int* p = (const int*)ei;
        g_src[e] = p[e];
        g_dst[e] = p[E + e];
    }
}

// ---------------------------------------------------------------------------
// degree / normalization
// ---------------------------------------------------------------------------
__global__ void k_init_deg(int n) {
    int i = blockIdx.x * blockDim.x + threadIdx.x;
    if (i < n) g_deg[i] = 1.0f;   // self-loop contributes 1
}

__global__ void k_count_deg(int E) {
    int e = blockIdx.x * blockDim.x + threadIdx.x;
    if (e < E) atomicAdd(&g_deg[g_dst[e]], 1.0f);
}

__global__ void k_dinv(int n) {
    int i = blockIdx.x * blockDim.x + threadIdx.x;
    if (i < n) g_dinv[i] = rsqrtf(g_deg[i]);
}

// ---------------------------------------------------------------------------
// Register-tiled fp32 GEMM:  Y[M,TN] = op(X)[M,128] * W[128,TN]
// 256 threads, 32-row tile, full-N tile. Per-thread 4x4 (TN=128) or 2x4 (TN=64).
// PRELU: input from g_agg1 with x -> max(x + bias_in[col], 0) on load; out g_h2.
// ---------------------------------------------------------------------------
template <int TN, bool PRELU>
__global__ void k_gemm(const float* __restrict__ Xin, const float* __restrict__ W,
                       const float* __restrict__ bias_in, int M)
{
    constexpr int KC  = 64;
    constexpr int CG  = TN / 4;
    constexpr int RPT = (32 * TN) / 1024;

    const float* __restrict__ X = PRELU ? (const float*)g_agg1 : Xin;
    float* __restrict__ Y       = PRELU ? g_h2 : g_h1;

    __shared__ float xs[32][KC];
    __shared__ float ws[KC][TN];

    const int tid = threadIdx.x;
    const int m0  = blockIdx.x * 32;
    const int cg  = tid % CG;
    const int rg  = tid / CG;

    float acc[RPT][4];
#pragma unroll
    for (int i = 0; i < RPT; i++) { acc[i][0]=acc[i][1]=acc[i][2]=acc[i][3]=0.f; }

    for (int kc = 0; kc < 128; kc += KC) {
        for (int t = tid; t < 32 * (KC / 4); t += 256) {
            int r  = t / (KC / 4);
            int kv = (t % (KC / 4)) * 4;
            int row = m0 + r;
            float4 v = make_float4(0.f, 0.f, 0.f, 0.f);
            if (row < M) v = *(const float4*)&X[row * 128 + kc + kv];
            if (PRELU) {
                float4 b = *(const float4*)&bias_in[kc + kv];
                v.x = fmaxf(v.x + b.x, 0.f);
                v.y = fmaxf(v.y + b.y, 0.f);
                v.z = fmaxf(v.z + b.z, 0.f);
                v.w = fmaxf(v.w + b.w, 0.f);
            }
            *(float4*)&xs[r][kv] = v;
        }
        for (int t = tid; t < KC * (TN / 4); t += 256) {
            int kk = t / (TN / 4);
            int nv = (t % (TN / 4)) * 4;
            *(float4*)&ws[kk][nv] = *(const float4*)&W[(kc + kk) * TN + nv];
        }
        __syncthreads();

#pragma unroll
        for (int kk = 0; kk < KC; kk++) {
            float4 w = *(float4*)&ws[kk][cg * 4];
#pragma unroll
            for (int i = 0; i < RPT; i++) {
                float xv = xs[rg * RPT + i][kk];
                acc[i][0] = fmaf(xv, w.x, acc[i][0]);
                acc[i][1] = fmaf(xv, w.y, acc[i][1]);
                acc[i][2] = fmaf(xv, w.z, acc[i][2]);
                acc[i][3] = fmaf(xv, w.w, acc[i][3]);
            }
        }
        __syncthreads();
    }

#pragma unroll
    for (int i = 0; i < RPT; i++) {
        int row = m0 + rg * RPT + i;
        if (row < M)
            *(float4*)&Y[row * TN + cg * 4] =
                make_float4(acc[i][0], acc[i][1], acc[i][2], acc[i][3]);
    }
}

// ---------------------------------------------------------------------------
// self-loop init:  agg1[i,:] = h1[i,:] * dinv[i]^2
// ---------------------------------------------------------------------------
__global__ void k_self128(int M)
{
    int i = blockIdx.x * blockDim.x + threadIdx.x;
    if (i < M * 32) {
        int node = i >> 5;
        float c = g_dinv[node]; c *= c;
        float4 v = ((const float4*)g_h1)[i];
        v.x *= c; v.y *= c; v.z *= c; v.w *= c;
        ((float4*)g_agg1)[i] = v;
    }
}

// out[i,:] = h2[i,:] * dinv[i]^2 + b2[:]
__global__ void k_selfout(const float* __restrict__ b2, float* __restrict__ out, int M)
{
    int i = blockIdx.x * blockDim.x + threadIdx.x;
    if (i < M * 16) {
        int node = i >> 4;
        int f4   = i & 15;
        float c = g_dinv[node]; c *= c;
        float4 v = ((const float4*)g_h2)[i];
        float4 b = ((const float4*)b2)[f4];
        v.x = fmaf(v.x, c, b.x);
        v.y = fmaf(v.y, c, b.y);
        v.z = fmaf(v.z, c, b.z);
        v.w = fmaf(v.w, c, b.w);
        ((float4*)out)[i] = v;
    }
}

// ---------------------------------------------------------------------------
// Edge scatter: one warp per edge.  agg[dst,:] += H[src,:] * dinv[s]*dinv[d]
// ---------------------------------------------------------------------------
template <int F>
__global__ void k_scatter(float* __restrict__ outp, int E)
{
    int gid  = blockIdx.x * blockDim.x + threadIdx.x;
    int e    = gid >> 5;
    int lane = gid & 31;
    if (e >= E) return;
    int s = g_src[e];
    int d = g_dst[e];
    float c = g_dinv[s] * g_dinv[d];
    if (F == 128) {
        float4 v = *(const float4*)&g_h1[s * 128 + lane * 4];
        float* a = &g_agg1[d * 128 + lane * 4];
        atomicAdd(a + 0, v.x * c);
        atomicAdd(a + 1, v.y * c);
        atomicAdd(a + 2, v.z * c);
        atomicAdd(a + 3, v.w * c);
    } else {
        float2 v = *(const float2*)&g_h2[s * 64 + lane * 2];
        float* a = &outp[d * 64 + lane * 2];
        atomicAdd(a + 0, v.x * c);
        atomicAdd(a + 1, v.y * c);
    }
}

// ---------------------------------------------------------------------------
extern "C" void kernel_launch(void* const* d_in, const int* in_sizes, int n_in,
                              void* d_out, int out_size)
{
    const float* x  = (const float*)d_in[0];
    const void*  ei = d_in[1];
    const float* W1 = (const float*)d_in[2];
    const float* b1 = (const float*)d_in[3];
    const float* W2 = (const float*)d_in[4];
    const float* b2 = (const float*)d_in[5];
    float*       out = (float*)d_out;

    const int M = in_sizes[0] / INF;   // 50000
    const int E = in_sizes[1] / 2;     // 800000

    const int T = 256;

    // 0. detect edge dtype + decode edges to int32
    k_probe <<<1, 256>>>((const int*)ei, in_sizes[1]);
    k_decode<<<(E + T - 1) / T, T>>>(ei, E);

    // 1. degree (with self-loop) -> dinv
    k_init_deg <<<(M + T - 1) / T, T>>>(M);
    k_count_deg<<<(E + T - 1) / T, T>>>(E);
    k_dinv     <<<(M + T - 1) / T, T>>>(M);

    // 2. layer 1: h1 = X @ W1
    k_gemm<128, false><<<(M + 31) / 32, 256>>>(x, W1, b1, M);

    // 3. aggregate layer 1
    k_self128<<<(M * 32 + T - 1) / T, T>>>(M);
    {
        long long tot = (long long)E * 32;
        k_scatter<128><<<(int)((tot + T - 1) / T), T>>>(nullptr, E);
    }

    // 4. layer 2: h2 = relu(agg1 + b1) @ W2
    k_gemm<64, true><<<(M + 31) / 32, 256>>>(nullptr, W2, b1, M);

    // 5. aggregate layer 2 into out
    k_selfout<<<(M * 16 + T - 1) / T, T>>>(b2, out, M);
    {
        long long tot = (long long)E * 32;
        k_scatter<64><<<(int)((tot + T - 1) / T), T>>>(out, E);
    }
}

// round 4
// speedup vs baseline: 1.6264x; 1.6264x over previous
#include <cuda_runtime.h>
#include <cuda_bf16.h>

// ---------------------------------------------------------------------------
// 2-layer GCN, pull-based aggregation via on-device CSR build (no fp atomics).
// ---------------------------------------------------------------------------

#define NMAX   50048
#define EMAX   800000
#define INF    128
#define OUTF   64

__device__ int   g_is64;
__device__ int   g_src [EMAX];
__device__ int   g_dst [EMAX];
__device__ int   g_cnt [NMAX];        // in-degree (without self loop)
__device__ int   g_ptr [NMAX + 1];    // CSR row pointers
__device__ int   g_fill[NMAX];        // fill cursors
__device__ int2  g_edge[EMAX];        // packed (src, __float_as_int(coeff))
__device__ float g_dinv[NMAX];
__device__ float g_h1  [NMAX * INF];  // X @ W1
__device__ float g_agg1[NMAX * INF];  // aggregated layer-1 (pre bias/relu)
__device__ float g_h2  [NMAX * OUTF]; // relu(agg1+b1) @ W2

// ---------------------------------------------------------------------------
// dtype probe: int64 indices < 2^31 have all odd (high) 32-bit words == 0.
// ---------------------------------------------------------------------------
__global__ void k_probe(const int* __restrict__ w32, int words) {
    __shared__ int viol;
    if (threadIdx.x == 0) viol = 0;
    __syncthreads();
    int nchk = words / 2;
    if (nchk > 32768) nchk = 32768;
    int bad = 0;
    for (int i = threadIdx.x; i < nchk; i += blockDim.x)
        if (w32[2 * i + 1] != 0) bad = 1;
    if (bad) atomicOr(&viol, 1);
    __syncthreads();
    if (threadIdx.x == 0) g_is64 = (viol == 0) ? 1 : 0;
}

__global__ void k_zero_cnt(int n) {
    int i = blockIdx.x * blockDim.x + threadIdx.x;
    if (i < n) g_cnt[i] = 0;
}

// decode edges to int32 + histogram destinations
__global__ void k_decode_count(const void* __restrict__ ei, int E) {
    int e = blockIdx.x * blockDim.x + threadIdx.x;
    if (e >= E) return;
    int s, d;
    if (g_is64) {
        const long long* p = (const long long*)ei;
        s = (int)p[e];  d = (int)p[E + e];
    } else {
        const int* p = (const int*)ei;
        s = p[e];       d = p[E + e];
    }
    g_src[e] = s;
    g_dst[e] = d;
    atomicAdd(&g_cnt[d], 1);
}

__global__ void k_dinv(int n) {
    int i = blockIdx.x * blockDim.x + threadIdx.x;
    if (i < n) g_dinv[i] = rsqrtf((float)(g_cnt[i] + 1));   // +1 self loop
}

// single-block exclusive prefix scan of g_cnt -> g_ptr / g_fill
__global__ void k_scan(int n) {
    __shared__ int ssum[1024];
    const int tid   = threadIdx.x;
    const int chunk = (n + 1023) / 1024;
    const int lo    = tid * chunk;
    const int hi    = min(lo + chunk, n);
    int s = 0;
    for (int i = lo; i < hi; i++) s += g_cnt[i];
    ssum[tid] = s;
    __syncthreads();
    int v = s;
    for (int off = 1; off < 1024; off <<= 1) {
        int t = (tid >= off) ? ssum[tid - off] : 0;
        __syncthreads();
        ssum[tid] += t;
        __syncthreads();
    }
    int run = ssum[tid] - v;    // exclusive prefix of this chunk
    for (int i = lo; i < hi; i++) {
        int c = g_cnt[i];
        g_ptr[i]  = run;
        g_fill[i] = run;
        run += c;
    }
    if (hi == n && lo <= n) g_ptr[n] = run;
}

// fill CSR with packed (src, coeff)
__global__ void k_fillcsr(int E) {
    int e = blockIdx.x * blockDim.x + threadIdx.x;
    if (e >= E) return;
    int s = g_src[e];
    int d = g_dst[e];
    float c = g_dinv[s] * g_dinv[d];
    int pos = atomicAdd(&g_fill[d], 1);
    g_edge[pos] = make_int2(s, __float_as_int(c));
}

// ---------------------------------------------------------------------------
// Register-tiled fp32 GEMM:  Y[M,TN] = op(X)[M,128] * W[128,TN]
// ---------------------------------------------------------------------------
template <int TN, bool PRELU>
__global__ void k_gemm(const float* __restrict__ Xin, const float* __restrict__ W,
                       const float* __restrict__ bias_in, int M)
{
    constexpr int KC  = 64;
    constexpr int CG  = TN / 4;
    constexpr int RPT = (32 * TN) / 1024;

    const float* __restrict__ X = PRELU ? (const float*)g_agg1 : Xin;
    float* __restrict__ Y       = PRELU ? g_h2 : g_h1;

    __shared__ float xs[32][KC];
    __shared__ float ws[KC][TN];

    const int tid = threadIdx.x;
    const int m0  = blockIdx.x * 32;
    const int cg  = tid % CG;
    const int rg  = tid / CG;

    float acc[RPT][4];
#pragma unroll
    for (int i = 0; i < RPT; i++) { acc[i][0]=acc[i][1]=acc[i][2]=acc[i][3]=0.f; }

    for (int kc = 0; kc < 128; kc += KC) {
        for (int t = tid; t < 32 * (KC / 4); t += 256) {
            int r  = t / (KC / 4);
            int kv = (t % (KC / 4)) * 4;
            int row = m0 + r;
            float4 v = make_float4(0.f, 0.f, 0.f, 0.f);
            if (row < M) v = *(const float4*)&X[row * 128 + kc + kv];
            if (PRELU) {
                float4 b = *(const float4*)&bias_in[kc + kv];
                v.x = fmaxf(v.x + b.x, 0.f);
                v.y = fmaxf(v.y + b.y, 0.f);
                v.z = fmaxf(v.z + b.z, 0.f);
                v.w = fmaxf(v.w + b.w, 0.f);
            }
            *(float4*)&xs[r][kv] = v;
        }
        for (int t = tid; t < KC * (TN / 4); t += 256) {
            int kk = t / (TN / 4);
            int nv = (t % (TN / 4)) * 4;
            *(float4*)&ws[kk][nv] = *(const float4*)&W[(kc + kk) * TN + nv];
        }
        __syncthreads();

#pragma unroll
        for (int kk = 0; kk < KC; kk++) {
            float4 w = *(float4*)&ws[kk][cg * 4];
#pragma unroll
            for (int i = 0; i < RPT; i++) {
                float xv = xs[rg * RPT + i][kk];
                acc[i][0] = fmaf(xv, w.x, acc[i][0]);
                acc[i][1] = fmaf(xv, w.y, acc[i][1]);
                acc[i][2] = fmaf(xv, w.z, acc[i][2]);
                acc[i][3] = fmaf(xv, w.w, acc[i][3]);
            }
        }
        __syncthreads();
    }

#pragma unroll
    for (int i = 0; i < RPT; i++) {
        int row = m0 + rg * RPT + i;
        if (row < M)
            *(float4*)&Y[row * TN + cg * 4] =
                make_float4(acc[i][0], acc[i][1], acc[i][2], acc[i][3]);
    }
}

// ---------------------------------------------------------------------------
// Pull aggregation, one warp per node.
// F=128: lane owns float4 of h1 -> agg1 = h1[n]*dinv^2 + sum(coeff*h1[src])
// F=64 : lane owns float2 of h2 -> out  = b2 + h2[n]*dinv^2 + sum(coeff*h2[src])
// ---------------------------------------------------------------------------
__global__ void k_gather128(int M)
{
    int w    = (blockIdx.x * blockDim.x + threadIdx.x) >> 5;
    int lane = threadIdx.x & 31;
    if (w >= M) return;
    const float4* __restrict__ H = (const float4*)g_h1;
    int beg = g_ptr[w], end = g_ptr[w + 1];
    float cs = g_dinv[w]; cs *= cs;
    float4 v = H[w * 32 + lane];
    float4 a0 = make_float4(v.x * cs, v.y * cs, v.z * cs, v.w * cs);
    float4 a1 = make_float4(0.f, 0.f, 0.f, 0.f);
    int e = beg;
    for (; e + 1 < end; e += 2) {
        int2 p0 = g_edge[e];
        int2 p1 = g_edge[e + 1];
        float c0 = __int_as_float(p0.y);
        float c1 = __int_as_float(p1.y);
        float4 v0 = H[p0.x * 32 + lane];
        float4 v1 = H[p1.x * 32 + lane];
        a0.x = fmaf(v0.x, c0, a0.x); a0.y = fmaf(v0.y, c0, a0.y);
        a0.z = fmaf(v0.z, c0, a0.z); a0.w = fmaf(v0.w, c0, a0.w);
        a1.x = fmaf(v1.x, c1, a1.x); a1.y = fmaf(v1.y, c1, a1.y);
        a1.z = fmaf(v1.z, c1, a1.z); a1.w = fmaf(v1.w, c1, a1.w);
    }
    if (e < end) {
        int2 p0 = g_edge[e];
        float c0 = __int_as_float(p0.y);
        float4 v0 = H[p0.x * 32 + lane];
        a0.x = fmaf(v0.x, c0, a0.x); a0.y = fmaf(v0.y, c0, a0.y);
        a0.z = fmaf(v0.z, c0, a0.z); a0.w = fmaf(v0.w, c0, a0.w);
    }
    a0.x += a1.x; a0.y += a1.y; a0.z += a1.z; a0.w += a1.w;
    ((float4*)g_agg1)[w * 32 + lane] = a0;
}

__global__ void k_gather64(const float* __restrict__ b2, float* __restrict__ outp, int M)
{
    int w    = (blockIdx.x * blockDim.x + threadIdx.x) >> 5;
    int lane = threadIdx.x & 31;
    if (w >= M) return;
    const float2* __restrict__ H = (const float2*)g_h2;
    int beg = g_ptr[w], end = g_ptr[w + 1];
    float cs = g_dinv[w]; cs *= cs;
    float2 v = H[w * 32 + lane];
    float2 bb = ((const float2*)b2)[lane];
    float2 a0 = make_float2(fmaf(v.x, cs, bb.x), fmaf(v.y, cs, bb.y));
    float2 a1 = make_float2(0.f, 0.f);
    int e = beg;
    for (; e + 1 < end; e += 2) {
        int2 p0 = g_edge[e];
        int2 p1 = g_edge[e + 1];
        float c0 = __int_as_float(p0.y);
        float c1 = __int_as_float(p1.y);
        float2 v0 = H[p0.x * 32 + lane];
        float2 v1 = H[p1.x * 32 + lane];
        a0.x = fmaf(v0.x, c0, a0.x); a0.y = fmaf(v0.y, c0, a0.y);
        a1.x = fmaf(v1.x, c1, a1.x); a1.y = fmaf(v1.y, c1, a1.y);
    }
    if (e < end) {
        int2 p0 = g_edge[e];
        float c0 = __int_as_float(p0.y);
        float2 v0 = H[p0.x * 32 + lane];
        a0.x = fmaf(v0.x, c0, a0.x); a0.y = fmaf(v0.y, c0, a0.y);
    }
    a0.x += a1.x; a0.y += a1.y;
    ((float2*)outp)[w * 32 + lane] = a0;
}

// ---------------------------------------------------------------------------
extern "C" void kernel_launch(void* const* d_in, const int* in_sizes, int n_in,
                              void* d_out, int out_size)
{
    const float* x  = (const float*)d_in[0];
    const void*  ei = d_in[1];
    const float* W1 = (const float*)d_in[2];
    const float* b1 = (const float*)d_in[3];
    const float* W2 = (const float*)d_in[4];
    const float* b2 = (const float*)d_in[5];
    float*       out = (float*)d_out;

    const int M = in_sizes[0] / INF;   // 50000
    const int E = in_sizes[1] / 2;     // 800000

    const int T = 256;

    // 0. dtype probe + decode + degree histogram
    k_probe       <<<1, 256>>>((const int*)ei, in_sizes[1]);
    k_zero_cnt    <<<(M + T - 1) / T, T>>>(M);
    k_decode_count<<<(E + T - 1) / T, T>>>(ei, E);

    // 1. normalization + CSR build
    k_dinv   <<<(M + T - 1) / T, T>>>(M);
    k_scan   <<<1, 1024>>>(M);
    k_fillcsr<<<(E + T - 1) / T, T>>>(E);

    // 2. layer 1: h1 = X @ W1 ; pull-aggregate into agg1
    k_gemm<128, false><<<(M + 31) / 32, 256>>>(x, W1, b1, M);
    k_gather128<<<(M * 32 + T - 1) / T, T>>>(M);

    // 3. layer 2: h2 = relu(agg1 + b1) @ W2 ; pull-aggregate + bias into out
    k_gemm<64, true><<<(M + 31) / 32, 256>>>(nullptr, W2, b1, M);
    k_gather64<<<(M * 32 + T - 1) / T, T>>>(b2, out, M);
}